// round 4
// baseline (speedup 1.0000x reference)
#include <cuda_runtime.h>
#include <cstdint>

// Literal implementation of the reference einsum, reading the provided weight:
//   out[s,b,o,h,w] = sum_n  adc_real[b,n,h,w] * W[s*256+o, n]
//                        +  adc_imag[b,n,h,w] * W[s*256+o, 256+n]
// in:  adc_real/adc_imag (4,256,256,256) f32,  W (512,512) f32
// out: (2,4,256,256,256) f32
//
// Correct-by-construction GEMM: M=512 outputs, K=512, N=262144 columns.
// CTA = 128 threads: 128 contiguous hw-columns x 64 outputs, K chunked by 64
// through smem (padded 68-float rows: conflict-free broadcast, 16B-aligned).

#define HW    65536     // 256*256
#define NFFT  256
#define KTOT  512
#define KC    64        // K chunk
#define MO    64        // outputs per CTA
#define NC    128       // columns per CTA

__global__ __launch_bounds__(NC)
void fft_gemm_kernel(const float* __restrict__ xr,
                     const float* __restrict__ xi,
                     const float* __restrict__ w,
                     float* __restrict__ out) {
    __shared__ float ws[KC][68];   // [kc][o_local], padded row (68*4=272B, 16B-aligned)

    const int tid = threadIdx.x;
    const int c   = blockIdx.x * NC + tid;   // hw column, coalesced per warp
    const int o0  = blockIdx.y * MO;         // output-row tile (0..511 in 8 tiles)
    const int b   = blockIdx.z;              // batch

    const float* __restrict__ xrb = xr + (size_t)b * NFFT * HW + c;
    const float* __restrict__ xib = xi + (size_t)b * NFFT * HW + c;

    float acc[MO];
    #pragma unroll
    for (int i = 0; i < MO; i++) acc[i] = 0.0f;

    for (int k0 = 0; k0 < KTOT; k0 += KC) {
        __syncthreads();
        // stage W[o0..o0+64)[k0..k0+64) as ws[kc][o_local]
        // consecutive tid -> consecutive kc -> coalesced gmem reads
        #pragma unroll
        for (int i = 0; i < (KC * MO) / NC; i++) {
            const int idx = i * NC + tid;
            const int kc  = idx & (KC - 1);
            const int ol  = idx >> 6;          // idx / KC
            ws[kc][ol] = w[(size_t)(o0 + ol) * KTOT + (k0 + kc)];
        }
        __syncthreads();

        // chunks are 64-aligned, so k<256 vs k>=256 is uniform per chunk
        const float* __restrict__ xsrc = (k0 < NFFT) ? (xrb + (size_t)k0 * HW)
                                                     : (xib + (size_t)(k0 - NFFT) * HW);
        #pragma unroll 8
        for (int kc = 0; kc < KC; kc++) {
            const float xv = xsrc[(size_t)kc * HW];
            const float4* __restrict__ row = (const float4*)ws[kc];
            #pragma unroll
            for (int j = 0; j < MO / 4; j++) {
                const float4 wv = row[j];      // broadcast LDS.128
                acc[4*j + 0] = fmaf(wv.x, xv, acc[4*j + 0]);
                acc[4*j + 1] = fmaf(wv.y, xv, acc[4*j + 1]);
                acc[4*j + 2] = fmaf(wv.z, xv, acc[4*j + 2]);
                acc[4*j + 3] = fmaf(wv.w, xv, acc[4*j + 3]);
            }
        }
    }

    // out[s,b,o,hw]: O = o0+ol -> s = O>>8, o = O&255
    #pragma unroll
    for (int ol = 0; ol < MO; ol++) {
        const int O = o0 + ol;
        const int s = O >> 8;
        const int o = O & 255;
        out[(size_t)s * (4u * NFFT * (size_t)HW)
          + (size_t)b * (NFFT * (size_t)HW)
          + (size_t)o * HW + c] = acc[ol];
    }
}

extern "C" void kernel_launch(void* const* d_in, const int* in_sizes, int n_in,
                              void* d_out, int out_size) {
    // identify buffers by element count (metadata order among equals preserved):
    // two 67,108,864-element arrays = adc_real, adc_imag; 262,144 = weight
    const float* xr = nullptr;
    const float* xi = nullptr;
    const float* w  = nullptr;
    for (int i = 0; i < n_in; i++) {
        if (in_sizes[i] == 4 * NFFT * HW) {
            if (!xr)      xr = (const float*)d_in[i];
            else if (!xi) xi = (const float*)d_in[i];
        } else if (in_sizes[i] == KTOT * KTOT) {
            w = (const float*)d_in[i];
        }
    }
    float* out = (float*)d_out;

    dim3 grid(HW / NC, KTOT / MO, 4);   // (512, 8, 4)
    fft_gemm_kernel<<<grid, NC>>>(xr, xi, w, out);
}

// round 6
// speedup vs baseline: 5.6518x; 5.6518x over previous
#include <cuda_runtime.h>
#include <cstdint>

// out[s,b,o,hw] = sum_k adc_real[b,k,hw]*W[s*256+o,k] + adc_imag[b,k,hw]*W[s*256+o,256+k]
// GEMM D[512, 4*65536] = W[512,512] * X[512,*] via legacy mma.sync tf32 HMMA
// (tcgen05 unavailable: harness compiles PTX at .target sm_103, no 'a' features).
//
// CTA 256 thr: tile 128o x 128hw, K chunks of 32, double-buffered smem,
// register prefetch, tf32 round-to-nearest at fill, direct STG.64 epilogue.

#define NFFT 256
#define HW   65536
#define KTOT 512
#define KC   32
#define MT   128      // o rows per CTA
#define NT   128      // hw cols per CTA
#define XP   136      // xs pitch (floats): conflict-free LDS for b-frags
#define WP   36       // ws pitch (floats): conflict-free LDS for a-frags

static __device__ __forceinline__ float tf32r(float x) {
    float r; asm("cvt.rna.tf32.f32 %0, %1;" : "=f"(r) : "f"(x)); return r;
}

#define MMA_TF32(d0,d1,d2,d3, a0,a1,a2,a3, b0,b1)                              \
    asm volatile("mma.sync.aligned.m16n8k8.row.col.f32.tf32.tf32.f32 "         \
        "{%0,%1,%2,%3}, {%4,%5,%6,%7}, {%8,%9}, {%0,%1,%2,%3};"                \
        : "+f"(d0), "+f"(d1), "+f"(d2), "+f"(d3)                               \
        : "r"(a0), "r"(a1), "r"(a2), "r"(a3), "r"(b0), "r"(b1))

__global__ __launch_bounds__(256, 1)
void fft_hmma_kernel(const float* __restrict__ xr,
                     const float* __restrict__ xi,
                     const float* __restrict__ w,
                     float* __restrict__ out) {
    extern __shared__ float smem[];
    float* ws = smem;                    // 2 stages x 128 x WP
    float* xs = smem + 2 * MT * WP;      // 2 stages x KC x XP

    const int tid  = threadIdx.x;
    const int lane = tid & 31;
    const int wid  = tid >> 5;
    const int wr   = wid & 3;            // o-warp   (4 x 32 = 128)
    const int wc   = wid >> 2;           // hw-warp  (2 x 64 = 128)
    const int ty   = lane >> 2;          // 0..7
    const int tx   = lane & 3;           // 0..3

    const int c0 = blockIdx.x * NT;
    const int o0 = blockIdx.y * MT;      // 0,128,256,384
    const int b  = blockIdx.z;

    // fill-role indices
    const int w_kq  = tid & 7;           // float4 slot in K (k = w_kq*4)
    const int w_or  = tid >> 3;          // o row 0..31, strided by 32
    const int x_c4  = (lane & 31) * 4;   // 4-col group
    const int x_kw  = tid >> 5;          // k row 0..7, strided by 8

    const size_t xoff = (size_t)b * NFFT * HW + c0 + x_c4;

    float acc[2][8][4];
    #pragma unroll
    for (int mt = 0; mt < 2; mt++)
        #pragma unroll
        for (int nt = 0; nt < 8; nt++)
            #pragma unroll
            for (int q = 0; q < 4; q++) acc[mt][nt][q] = 0.0f;

    float4 pw[4], px[4];

    // ---- prefetch chunk 0 ----
    {
        const float* wsrc = w + o0 * KTOT;
        #pragma unroll
        for (int r = 0; r < 4; r++)
            pw[r] = *(const float4*)(wsrc + (size_t)(w_or + r * 32) * KTOT + w_kq * 4);
        const float* xsrc = xr + xoff;
        #pragma unroll
        for (int p = 0; p < 4; p++)
            px[p] = *(const float4*)(xsrc + (size_t)(p * 8 + x_kw) * HW);
    }
    // ---- store chunk 0 to stage 0 ----
    #pragma unroll
    for (int r = 0; r < 4; r++) {
        float4 v = pw[r];
        v.x = tf32r(v.x); v.y = tf32r(v.y); v.z = tf32r(v.z); v.w = tf32r(v.w);
        *(float4*)(ws + (w_or + r * 32) * WP + w_kq * 4) = v;
    }
    #pragma unroll
    for (int p = 0; p < 4; p++) {
        float4 v = px[p];
        v.x = tf32r(v.x); v.y = tf32r(v.y); v.z = tf32r(v.z); v.w = tf32r(v.w);
        *(float4*)(xs + (p * 8 + x_kw) * XP + x_c4) = v;
    }

    for (int i = 0; i < KTOT / KC; i++) {
        __syncthreads();
        const int s = i & 1;

        // prefetch chunk i+1 into registers
        if (i < 15) {
            const int ki = i + 1;
            const float* wsrc = w + o0 * KTOT + ki * KC;
            #pragma unroll
            for (int r = 0; r < 4; r++)
                pw[r] = *(const float4*)(wsrc + (size_t)(w_or + r * 32) * KTOT + w_kq * 4);
            const float* xsrc = ((ki < 8) ? xr : xi) + xoff + (size_t)((ki & 7) * KC) * HW;
            #pragma unroll
            for (int p = 0; p < 4; p++)
                px[p] = *(const float4*)(xsrc + (size_t)(p * 8 + x_kw) * HW);
        }

        // compute chunk i from stage s
        const float* wst = ws + s * MT * WP;
        const float* xst = xs + s * KC * XP;
        #pragma unroll
        for (int kk = 0; kk < KC; kk += 8) {
            uint32_t af[2][4], bf[8][2];
            #pragma unroll
            for (int mt = 0; mt < 2; mt++) {
                const float* ap = wst + (wr * 32 + mt * 16 + ty) * WP + kk + tx;
                af[mt][0] = __float_as_uint(ap[0]);
                af[mt][1] = __float_as_uint(ap[8 * WP]);
                af[mt][2] = __float_as_uint(ap[4]);
                af[mt][3] = __float_as_uint(ap[8 * WP + 4]);
            }
            #pragma unroll
            for (int nt = 0; nt < 8; nt++) {
                const float* bp = xst + (kk + tx) * XP + wc * 64 + nt * 8 + ty;
                bf[nt][0] = __float_as_uint(bp[0]);
                bf[nt][1] = __float_as_uint(bp[4 * XP]);
            }
            #pragma unroll
            for (int mt = 0; mt < 2; mt++)
                #pragma unroll
                for (int nt = 0; nt < 8; nt++)
                    MMA_TF32(acc[mt][nt][0], acc[mt][nt][1], acc[mt][nt][2], acc[mt][nt][3],
                             af[mt][0], af[mt][1], af[mt][2], af[mt][3],
                             bf[nt][0], bf[nt][1]);
        }

        // store chunk i+1 into the other stage (safe: it was last read in
        // chunk i-1, all reads done before this iteration's syncthreads)
        if (i < 15) {
            float* wd = ws + (1 - s) * MT * WP;
            float* xd = xs + (1 - s) * KC * XP;
            #pragma unroll
            for (int r = 0; r < 4; r++) {
                float4 v = pw[r];
                v.x = tf32r(v.x); v.y = tf32r(v.y); v.z = tf32r(v.z); v.w = tf32r(v.w);
                *(float4*)(wd + (w_or + r * 32) * WP + w_kq * 4) = v;
            }
            #pragma unroll
            for (int p = 0; p < 4; p++) {
                float4 v = px[p];
                v.x = tf32r(v.x); v.y = tf32r(v.y); v.z = tf32r(v.z); v.w = tf32r(v.w);
                *(float4*)(xd + (p * 8 + x_kw) * XP + x_c4) = v;
            }
        }
    }

    // ---- epilogue: direct STG.64 ----
    // global row O = o0 + wr*32 + mt*16 + ty (+8); s-plane and o-in-plane are
    // uniform per CTA since o0 is a multiple of 128.
    const int sp = blockIdx.y >> 1;
    float* outp = out + ((size_t)(sp * 4 + b) * NFFT + (o0 & 255)) * (size_t)HW
                + c0 + wc * 64;
    #pragma unroll
    for (int mt = 0; mt < 2; mt++) {
        const int r0 = wr * 32 + mt * 16 + ty;
        #pragma unroll
        for (int nt = 0; nt < 8; nt++) {
            const int col = nt * 8 + tx * 2;
            float2 v0 = make_float2(acc[mt][nt][0], acc[mt][nt][1]);
            float2 v1 = make_float2(acc[mt][nt][2], acc[mt][nt][3]);
            *(float2*)(outp + (size_t)r0 * HW + col)       = v0;
            *(float2*)(outp + (size_t)(r0 + 8) * HW + col) = v1;
        }
    }
}

extern "C" void kernel_launch(void* const* d_in, const int* in_sizes, int n_in,
                              void* d_out, int out_size) {
    // buffer identification by size (verified exact in R4)
    const float* xr = nullptr;
    const float* xi = nullptr;
    const float* w  = nullptr;
    for (int i = 0; i < n_in; i++) {
        if (in_sizes[i] == 4 * NFFT * HW) {
            if (!xr)      xr = (const float*)d_in[i];
            else if (!xi) xi = (const float*)d_in[i];
        } else if (in_sizes[i] == KTOT * KTOT) {
            w = (const float*)d_in[i];
        }
    }
    float* out = (float*)d_out;

    const int smem_bytes = 2 * (MT * WP + KC * XP) * 4;   // 71680
    cudaFuncSetAttribute(fft_hmma_kernel, cudaFuncAttributeMaxDynamicSharedMemorySize, smem_bytes);
    dim3 grid(HW / NT, KTOT / MT, 4);   // (512, 4, 4)
    fft_hmma_kernel<<<grid, 256, smem_bytes>>>(xr, xi, w, out);
}

// round 7
// speedup vs baseline: 6.8174x; 1.2062x over previous
#include <cuda_runtime.h>
#include <cstdint>

// out[s,b,o,hw] = sum_k adc_real[b,k,hw]*W[s*256+o,k] + adc_imag[b,k,hw]*W[s*256+o,256+k]
// GEMM D[512, 4*65536] = W[512,512] * X[512,*] via legacy mma.sync tf32 HMMA.
// R7: CTA tile 256o x 128hw (8 warps, warp tile 64x64) -> 8 MAC per shared byte,
// tensor-bound. K chunks of 32, double-buffered smem, register prefetch,
// tf32 round-to-nearest at fill, direct STG.64 epilogue.

#define NFFT 256
#define HW   65536
#define KTOT 512
#define KC   32
#define MT   256      // o rows per CTA
#define NT   128      // hw cols per CTA
#define XP   136      // xs pitch (floats)
#define WP   36       // ws pitch (floats)

static __device__ __forceinline__ float tf32r(float x) {
    float r; asm("cvt.rna.tf32.f32 %0, %1;" : "=f"(r) : "f"(x)); return r;
}

#define MMA_TF32(d0,d1,d2,d3, a0,a1,a2,a3, b0,b1)                              \
    asm volatile("mma.sync.aligned.m16n8k8.row.col.f32.tf32.tf32.f32 "         \
        "{%0,%1,%2,%3}, {%4,%5,%6,%7}, {%8,%9}, {%0,%1,%2,%3};"                \
        : "+f"(d0), "+f"(d1), "+f"(d2), "+f"(d3)                               \
        : "r"(a0), "r"(a1), "r"(a2), "r"(a3), "r"(b0), "r"(b1))

__global__ __launch_bounds__(256, 1)
void fft_hmma_kernel(const float* __restrict__ xr,
                     const float* __restrict__ xi,
                     const float* __restrict__ w,
                     float* __restrict__ out) {
    extern __shared__ float smem[];
    float* ws = smem;                    // 2 stages x MT x WP
    float* xs = smem + 2 * MT * WP;      // 2 stages x KC x XP

    const int tid  = threadIdx.x;
    const int lane = tid & 31;
    const int wid  = tid >> 5;
    const int wr   = wid & 3;            // M-warp: 4 x 64 = 256
    const int wc   = wid >> 2;           // N-warp: 2 x 64 = 128
    const int ty   = lane >> 2;          // 0..7
    const int tx   = lane & 3;           // 0..3

    const int c0 = blockIdx.x * NT;
    const int by = blockIdx.y;           // 0,1 -> o0 = by*256; s-plane = by
    const int o0 = by * MT;
    const int b  = blockIdx.z;

    // fill-role indices
    const int w_kq = tid & 7;            // float4 slot in K
    const int w_or = tid >> 3;           // W row 0..31, strided by 32 (8 reps)
    const int x_c4 = lane * 4;           // 4-col group
    const int x_kw = wid;                // k row 0..7, strided by 8 (4 reps)

    const size_t xoff = (size_t)b * NFFT * HW + c0 + x_c4;

    float acc[4][8][4];
    #pragma unroll
    for (int mt = 0; mt < 4; mt++)
        #pragma unroll
        for (int nt = 0; nt < 8; nt++)
            #pragma unroll
            for (int q = 0; q < 4; q++) acc[mt][nt][q] = 0.0f;

    float4 pw[8], px[4];

    // ---- prefetch chunk 0 ----
    {
        const float* wsrc = w + (size_t)o0 * KTOT;
        #pragma unroll
        for (int r = 0; r < 8; r++)
            pw[r] = *(const float4*)(wsrc + (size_t)(w_or + r * 32) * KTOT + w_kq * 4);
        const float* xsrc = xr + xoff;
        #pragma unroll
        for (int p = 0; p < 4; p++)
            px[p] = *(const float4*)(xsrc + (size_t)(p * 8 + x_kw) * HW);
    }
    // ---- store chunk 0 to stage 0 ----
    #pragma unroll
    for (int r = 0; r < 8; r++) {
        float4 v = pw[r];
        v.x = tf32r(v.x); v.y = tf32r(v.y); v.z = tf32r(v.z); v.w = tf32r(v.w);
        *(float4*)(ws + (w_or + r * 32) * WP + w_kq * 4) = v;
    }
    #pragma unroll
    for (int p = 0; p < 4; p++) {
        float4 v = px[p];
        v.x = tf32r(v.x); v.y = tf32r(v.y); v.z = tf32r(v.z); v.w = tf32r(v.w);
        *(float4*)(xs + (p * 8 + x_kw) * XP + x_c4) = v;
    }

    for (int i = 0; i < KTOT / KC; i++) {
        __syncthreads();
        const int s = i & 1;

        // prefetch chunk i+1 into registers
        if (i < 15) {
            const int ki = i + 1;
            const float* wsrc = w + (size_t)o0 * KTOT + ki * KC;
            #pragma unroll
            for (int r = 0; r < 8; r++)
                pw[r] = *(const float4*)(wsrc + (size_t)(w_or + r * 32) * KTOT + w_kq * 4);
            const float* xsrc = ((ki < 8) ? xr : xi) + xoff + (size_t)((ki & 7) * KC) * HW;
            #pragma unroll
            for (int p = 0; p < 4; p++)
                px[p] = *(const float4*)(xsrc + (size_t)(p * 8 + x_kw) * HW);
        }

        // compute chunk i from stage s
        const float* wst = ws + s * MT * WP;
        const float* xst = xs + s * KC * XP;
        #pragma unroll
        for (int kk = 0; kk < KC; kk += 8) {
            uint32_t af[4][4], bf[8][2];
            #pragma unroll
            for (int mt = 0; mt < 4; mt++) {
                const float* ap = wst + (wr * 64 + mt * 16 + ty) * WP + kk + tx;
                af[mt][0] = __float_as_uint(ap[0]);
                af[mt][1] = __float_as_uint(ap[8 * WP]);
                af[mt][2] = __float_as_uint(ap[4]);
                af[mt][3] = __float_as_uint(ap[8 * WP + 4]);
            }
            #pragma unroll
            for (int nt = 0; nt < 8; nt++) {
                const float* bp = xst + (kk + tx) * XP + wc * 64 + nt * 8 + ty;
                bf[nt][0] = __float_as_uint(bp[0]);
                bf[nt][1] = __float_as_uint(bp[4 * XP]);
            }
            #pragma unroll
            for (int mt = 0; mt < 4; mt++)
                #pragma unroll
                for (int nt = 0; nt < 8; nt++)
                    MMA_TF32(acc[mt][nt][0], acc[mt][nt][1], acc[mt][nt][2], acc[mt][nt][3],
                             af[mt][0], af[mt][1], af[mt][2], af[mt][3],
                             bf[nt][0], bf[nt][1]);
        }

        // store chunk i+1 into the other stage
        if (i < 15) {
            float* wd = ws + (1 - s) * MT * WP;
            float* xd = xs + (1 - s) * KC * XP;
            #pragma unroll
            for (int r = 0; r < 8; r++) {
                float4 v = pw[r];
                v.x = tf32r(v.x); v.y = tf32r(v.y); v.z = tf32r(v.z); v.w = tf32r(v.w);
                *(float4*)(wd + (w_or + r * 32) * WP + w_kq * 4) = v;
            }
            #pragma unroll
            for (int p = 0; p < 4; p++) {
                float4 v = px[p];
                v.x = tf32r(v.x); v.y = tf32r(v.y); v.z = tf32r(v.z); v.w = tf32r(v.w);
                *(float4*)(xd + (p * 8 + x_kw) * XP + x_c4) = v;
            }
        }
    }

    // ---- epilogue: direct STG.64 ----
    // s-plane = by, o = local row (0..255)
    float* outp = out + ((size_t)(by * 4 + b) * NFFT) * (size_t)HW
                + c0 + wc * 64;
    #pragma unroll
    for (int mt = 0; mt < 4; mt++) {
        const int r0 = wr * 64 + mt * 16 + ty;
        #pragma unroll
        for (int nt = 0; nt < 8; nt++) {
            const int col = nt * 8 + tx * 2;
            float2 v0 = make_float2(acc[mt][nt][0], acc[mt][nt][1]);
            float2 v1 = make_float2(acc[mt][nt][2], acc[mt][nt][3]);
            *(float2*)(outp + (size_t)r0 * HW + col)       = v0;
            *(float2*)(outp + (size_t)(r0 + 8) * HW + col) = v1;
        }
    }
}

extern "C" void kernel_launch(void* const* d_in, const int* in_sizes, int n_in,
                              void* d_out, int out_size) {
    // buffer identification by size (verified exact in R4)
    const float* xr = nullptr;
    const float* xi = nullptr;
    const float* w  = nullptr;
    for (int i = 0; i < n_in; i++) {
        if (in_sizes[i] == 4 * NFFT * HW) {
            if (!xr)      xr = (const float*)d_in[i];
            else if (!xi) xi = (const float*)d_in[i];
        } else if (in_sizes[i] == KTOT * KTOT) {
            w = (const float*)d_in[i];
        }
    }
    float* out = (float*)d_out;

    const int smem_bytes = 2 * (MT * WP + KC * XP) * 4;   // 108544
    cudaFuncSetAttribute(fft_hmma_kernel, cudaFuncAttributeMaxDynamicSharedMemorySize, smem_bytes);
    dim3 grid(HW / NT, KTOT / MT, 4);   // (512, 2, 4)
    fft_hmma_kernel<<<grid, 256, smem_bytes>>>(xr, xi, w, out);
}

// round 8
// speedup vs baseline: 7.0257x; 1.0306x over previous
#include <cuda_runtime.h>
#include <cstdint>

// out[s,b,o,hw] = sum_k adc_real[b,k,hw]*W[s*256+o,k] + adc_imag[b,k,hw]*W[s*256+o,256+k]
// GEMM D[512, 4*65536] = W[512,512] * X[512,*] via mma.sync tf32 HMMA.
// R8: 3-stage cp.async pipeline for W (pre-rounded + k-pair-permuted into a
// __device__ buffer by a prep kernel), register fill for X (RNA-rounded),
// A-frags via LDS.64, CTA tile 256x128, warp tile 64x64.

#define NFFT 256
#define HW   65536
#define KTOT 512
#define KC   32
#define MT   256
#define NT   128
#define NSTG 3
#define XP   136                 // xs pitch (floats), conflict-free (verified R7)
#define WP   40                  // ws pitch (floats), conflict-free for LDS.64 pairs
#define WS_STAGE (MT * WP)       // floats per W stage  (10240)
#define XS_STAGE (KC * XP)       // floats per X stage  (4352)

__device__ float wprep[16 * 512 * 32];   // [k-chunk][row][pos], tf32-rounded, 1 MB

static __device__ __forceinline__ float tf32r(float x) {
    float r; asm("cvt.rna.tf32.f32 %0, %1;" : "=f"(r) : "f"(x)); return r;
}
static __device__ __forceinline__ uint32_t smem_u32(const void* p) {
    uint32_t a;
    asm("{ .reg .u64 t; cvta.to.shared.u64 t, %1; cvt.u32.u64 %0, t; }" : "=r"(a) : "l"(p));
    return a;
}

#define CP_ASYNC16(d, s) asm volatile("cp.async.cg.shared.global [%0], [%1], 16;" :: "r"(d), "l"(s))
#define CP_COMMIT()      asm volatile("cp.async.commit_group;" ::: "memory")
#define CP_WAIT1()       asm volatile("cp.async.wait_group 1;" ::: "memory")

#define MMA_TF32(d0,d1,d2,d3, a0,a1,a2,a3, b0,b1)                              \
    asm volatile("mma.sync.aligned.m16n8k8.row.col.f32.tf32.tf32.f32 "         \
        "{%0,%1,%2,%3}, {%4,%5,%6,%7}, {%8,%9}, {%0,%1,%2,%3};"                \
        : "+f"(d0), "+f"(d1), "+f"(d2), "+f"(d3)                               \
        : "r"(a0), "r"(a1), "r"(a2), "r"(a3), "r"(b0), "r"(b1))

// prep: round W to tf32 (RNA) and store k-pair-permuted per 32-k chunk:
// within each 8-k group, order [k0,k4,k1,k5,k2,k6,k3,k7] so (k,k+4) are adjacent.
__global__ void prep_w_kernel(const float* __restrict__ w) {
    const int idx = blockIdx.x * 256 + threadIdx.x;     // 0..262143
    const int row = idx >> 9;
    const int k   = idx & 511;
    const int kk  = k & 31;
    const int pos = ((kk >> 3) << 3) + 2 * (kk & 3) + ((kk & 7) >> 2);
    wprep[(((size_t)(k >> 5) * 512) + row) * 32 + pos] = tf32r(w[idx]);
}

__global__ __launch_bounds__(256, 1)
void fft_hmma_kernel(const float* __restrict__ xr,
                     const float* __restrict__ xi,
                     float* __restrict__ out) {
    extern __shared__ float smem[];
    float* ws = smem;                          // NSTG x WS_STAGE
    float* xs = smem + NSTG * WS_STAGE;        // NSTG x XS_STAGE
    const uint32_t ws_u32 = smem_u32(ws);

    const int tid  = threadIdx.x;
    const int lane = tid & 31;
    const int wid  = tid >> 5;
    const int wr   = wid & 3;                  // M-warp: 4 x 64 = 256
    const int wc   = wid >> 2;                 // N-warp: 2 x 64 = 128
    const int ty   = lane >> 2;
    const int tx   = lane & 3;

    const int c0 = blockIdx.x * NT;
    const int by = blockIdx.y;                 // s-plane; o0 = by*256
    const int o0 = by * MT;
    const int b  = blockIdx.z;

    // X fill roles (register path, proven in R7)
    const int x_c4 = lane * 4;
    const int x_kw = wid;
    const size_t xoff = (size_t)b * NFFT * HW + c0 + x_c4;

    // W cp.async roles: 2048 16B pieces per stage, 8 per thread
    const float* wsrc0 = wprep + (size_t)o0 * 32;

    float acc[4][8][4];
    #pragma unroll
    for (int mt = 0; mt < 4; mt++)
        #pragma unroll
        for (int nt = 0; nt < 8; nt++)
            #pragma unroll
            for (int q = 0; q < 4; q++) acc[mt][nt][q] = 0.0f;

    float4 px[4];

    // ---- prologue: W chunks 0,1 via cp.async; X chunks 0,1 via registers ----
    #pragma unroll
    for (int cpre = 0; cpre < 2; cpre++) {
        const float* src = wsrc0 + (size_t)cpre * 512 * 32;
        const uint32_t dst = ws_u32 + cpre * (WS_STAGE * 4);
        #pragma unroll
        for (int p = 0; p < 8; p++) {
            const int idx = p * 256 + tid;
            const int r = idx >> 3, j = idx & 7;
            CP_ASYNC16(dst + r * (WP * 4) + j * 16, src + r * 32 + j * 4);
        }
        CP_COMMIT();
    }
    #pragma unroll
    for (int cpre = 0; cpre < 2; cpre++) {
        const float* xsrcp = xr + xoff + (size_t)(cpre * KC) * HW;
        #pragma unroll
        for (int p = 0; p < 4; p++)
            px[p] = *(const float4*)(xsrcp + (size_t)(p * 8 + x_kw) * HW);
        float* xd = xs + cpre * XS_STAGE;
        #pragma unroll
        for (int p = 0; p < 4; p++) {
            float4 v = px[p];
            v.x = tf32r(v.x); v.y = tf32r(v.y); v.z = tf32r(v.z); v.w = tf32r(v.w);
            *(float4*)(xd + (p * 8 + x_kw) * XP + x_c4) = v;
        }
    }

    // frag base offsets
    const int abase = (wr * 64 + ty) * WP + 2 * tx;     // + mt*16*WP + kk
    const int bbase = tx * XP + wc * 64 + ty;           // + kk*XP + nt*8

    for (int i = 0; i < 16; i++) {
        CP_WAIT1();
        __syncthreads();

        const int ki = i + 2;
        if (ki < 16) {
            // W fill chunk ki -> stage ki%3 (consumed at iter i-1, safe)
            const float* src = wsrc0 + (size_t)ki * 512 * 32;
            const uint32_t dst = ws_u32 + (ki % NSTG) * (WS_STAGE * 4);
            #pragma unroll
            for (int p = 0; p < 8; p++) {
                const int idx = p * 256 + tid;
                const int r = idx >> 3, j = idx & 7;
                CP_ASYNC16(dst + r * (WP * 4) + j * 16, src + r * 32 + j * 4);
            }
            // X LDG chunk ki (latency hidden under compute below)
            const float* xsrcp = ((ki < 8) ? xr : xi) + xoff + (size_t)((ki & 7) * KC) * HW;
            #pragma unroll
            for (int p = 0; p < 4; p++)
                px[p] = *(const float4*)(xsrcp + (size_t)(p * 8 + x_kw) * HW);
        }
        CP_COMMIT();

        // ---- compute chunk i from stage i%3 ----
        const float* wst = ws + (i % NSTG) * WS_STAGE;
        const float* xst = xs + (i % NSTG) * XS_STAGE;
        #pragma unroll
        for (int kk = 0; kk < KC; kk += 8) {
            float2 a2[4][2];
            #pragma unroll
            for (int mt = 0; mt < 4; mt++) {
                const float* ap = wst + abase + mt * (16 * WP) + kk;
                a2[mt][0] = *(const float2*)ap;               // rows ty   : (k, k+4)
                a2[mt][1] = *(const float2*)(ap + 8 * WP);    // rows ty+8 : (k, k+4)
            }
            uint32_t bf[8][2];
            #pragma unroll
            for (int nt = 0; nt < 8; nt++) {
                const float* bp = xst + bbase + kk * XP + nt * 8;
                bf[nt][0] = __float_as_uint(bp[0]);
                bf[nt][1] = __float_as_uint(bp[4 * XP]);
            }
            #pragma unroll
            for (int mt = 0; mt < 4; mt++) {
                const uint32_t a0 = __float_as_uint(a2[mt][0].x);
                const uint32_t a1 = __float_as_uint(a2[mt][1].x);
                const uint32_t a2r = __float_as_uint(a2[mt][0].y);
                const uint32_t a3 = __float_as_uint(a2[mt][1].y);
                #pragma unroll
                for (int nt = 0; nt < 8; nt++)
                    MMA_TF32(acc[mt][nt][0], acc[mt][nt][1], acc[mt][nt][2], acc[mt][nt][3],
                             a0, a1, a2r, a3, bf[nt][0], bf[nt][1]);
            }
        }

        // ---- X STS chunk ki -> stage ki%3 ----
        if (ki < 16) {
            float* xd = xs + (ki % NSTG) * XS_STAGE;
            #pragma unroll
            for (int p = 0; p < 4; p++) {
                float4 v = px[p];
                v.x = tf32r(v.x); v.y = tf32r(v.y); v.z = tf32r(v.z); v.w = tf32r(v.w);
                *(float4*)(xd + (p * 8 + x_kw) * XP + x_c4) = v;
            }
        }
    }

    // ---- epilogue: direct STG.64 (layout verified in R7) ----
    float* outp = out + ((size_t)(by * 4 + b) * NFFT) * (size_t)HW + c0 + wc * 64;
    #pragma unroll
    for (int mt = 0; mt < 4; mt++) {
        const int r0 = wr * 64 + mt * 16 + ty;
        #pragma unroll
        for (int nt = 0; nt < 8; nt++) {
            const int col = nt * 8 + tx * 2;
            float2 v0 = make_float2(acc[mt][nt][0], acc[mt][nt][1]);
            float2 v1 = make_float2(acc[mt][nt][2], acc[mt][nt][3]);
            *(float2*)(outp + (size_t)r0 * HW + col)       = v0;
            *(float2*)(outp + (size_t)(r0 + 8) * HW + col) = v1;
        }
    }
}

extern "C" void kernel_launch(void* const* d_in, const int* in_sizes, int n_in,
                              void* d_out, int out_size) {
    const float* xr = nullptr;
    const float* xi = nullptr;
    const float* w  = nullptr;
    for (int i = 0; i < n_in; i++) {
        if (in_sizes[i] == 4 * NFFT * HW) {
            if (!xr)      xr = (const float*)d_in[i];
            else if (!xi) xi = (const float*)d_in[i];
        } else if (in_sizes[i] == KTOT * KTOT) {
            w = (const float*)d_in[i];
        }
    }
    float* out = (float*)d_out;

    prep_w_kernel<<<1024, 256>>>(w);

    const int smem_bytes = NSTG * (WS_STAGE + XS_STAGE) * 4;   // 175,104
    cudaFuncSetAttribute(fft_hmma_kernel, cudaFuncAttributeMaxDynamicSharedMemorySize, smem_bytes);
    dim3 grid(HW / NT, 2, 4);   // (512, 2, 4)
    fft_hmma_kernel<<<grid, 256, smem_bytes>>>(xr, xi, out);
}

// round 9
// speedup vs baseline: 7.3005x; 1.0391x over previous
#include <cuda_runtime.h>
#include <cstdint>

// out[s,b,o,hw] = sum_k adc_real[b,k,hw]*W[s*256+o,k] + adc_imag[b,k,hw]*W[s*256+o,256+k]
// GEMM D[512, 4*65536] = W[512,512] * X[512,*] via mma.sync tf32 HMMA.
// R9: 512 threads (16 warps, warp tile 64x32, 4Mx4N) to put 4 warps on each
// SMSP and hide pipeline-sync gaps; CTA tile 256x128, 3-stage cp.async W,
// register-fill X, RNA tf32 rounding, direct STG.64 epilogue.

#define NFFT 256
#define HW   65536
#define KTOT 512
#define KC   32
#define MT   256
#define NT   128
#define NSTG 3
#define XP   136                 // xs pitch (floats), conflict-free
#define WP   40                  // ws pitch (floats), conflict-free LDS.64 pairs
#define WS_STAGE (MT * WP)
#define XS_STAGE (KC * XP)

__device__ float wprep[16 * 512 * 32];   // [k-chunk][row][pos], tf32-rounded

static __device__ __forceinline__ float tf32r(float x) {
    float r; asm("cvt.rna.tf32.f32 %0, %1;" : "=f"(r) : "f"(x)); return r;
}
static __device__ __forceinline__ uint32_t smem_u32(const void* p) {
    uint32_t a;
    asm("{ .reg .u64 t; cvta.to.shared.u64 t, %1; cvt.u32.u64 %0, t; }" : "=r"(a) : "l"(p));
    return a;
}

#define CP_ASYNC16(d, s) asm volatile("cp.async.cg.shared.global [%0], [%1], 16;" :: "r"(d), "l"(s))
#define CP_COMMIT()      asm volatile("cp.async.commit_group;" ::: "memory")
#define CP_WAIT1()       asm volatile("cp.async.wait_group 1;" ::: "memory")

#define MMA_TF32(d0,d1,d2,d3, a0,a1,a2,a3, b0,b1)                              \
    asm volatile("mma.sync.aligned.m16n8k8.row.col.f32.tf32.tf32.f32 "         \
        "{%0,%1,%2,%3}, {%4,%5,%6,%7}, {%8,%9}, {%0,%1,%2,%3};"                \
        : "+f"(d0), "+f"(d1), "+f"(d2), "+f"(d3)                               \
        : "r"(a0), "r"(a1), "r"(a2), "r"(a3), "r"(b0), "r"(b1))

// prep: tf32-RNA-round W, store k-pair-permuted per 32-k chunk:
// within each 8-k group order [k0,k4,k1,k5,k2,k6,k3,k7] so (k,k+4) adjacent.
__global__ void prep_w_kernel(const float* __restrict__ w) {
    const int idx = blockIdx.x * 256 + threadIdx.x;
    const int row = idx >> 9;
    const int k   = idx & 511;
    const int kk  = k & 31;
    const int pos = ((kk >> 3) << 3) + 2 * (kk & 3) + ((kk & 7) >> 2);
    wprep[(((size_t)(k >> 5) * 512) + row) * 32 + pos] = tf32r(w[idx]);
}

__global__ __launch_bounds__(512, 1)
void fft_hmma_kernel(const float* __restrict__ xr,
                     const float* __restrict__ xi,
                     float* __restrict__ out) {
    extern __shared__ float smem[];
    float* ws = smem;
    float* xs = smem + NSTG * WS_STAGE;
    const uint32_t ws_u32 = smem_u32(ws);

    const int tid  = threadIdx.x;
    const int lane = tid & 31;
    const int wid  = tid >> 5;
    const int wr   = wid & 3;                 // M-warp: 4 x 64 = 256
    const int wc   = wid >> 2;                // N-warp: 4 x 32 = 128
    const int ty   = lane >> 2;
    const int tx   = lane & 3;

    const int c0 = blockIdx.x * NT;
    const int by = blockIdx.y;                // s-plane; o0 = by*256
    const int o0 = by * MT;
    const int b  = blockIdx.z;

    // X fill roles: 1024 float4 per stage / 512 thr = 2 each
    const int x_c4 = (tid & 31) * 4;
    const int x_kw = tid >> 5;                // 0..15
    const size_t xoff = (size_t)b * NFFT * HW + c0 + x_c4;

    const float* wsrc0 = wprep + (size_t)o0 * 32;

    float acc[4][4][4];
    #pragma unroll
    for (int mt = 0; mt < 4; mt++)
        #pragma unroll
        for (int nt = 0; nt < 4; nt++)
            #pragma unroll
            for (int q = 0; q < 4; q++) acc[mt][nt][q] = 0.0f;

    float4 px[2];

    // ---- prologue: W chunks 0,1 via cp.async; X chunks 0,1 via registers ----
    #pragma unroll
    for (int cpre = 0; cpre < 2; cpre++) {
        const float* src = wsrc0 + (size_t)cpre * 512 * 32;
        const uint32_t dst = ws_u32 + cpre * (WS_STAGE * 4);
        #pragma unroll
        for (int p = 0; p < 4; p++) {
            const int idx = p * 512 + tid;
            const int r = idx >> 3, j = idx & 7;
            CP_ASYNC16(dst + r * (WP * 4) + j * 16, src + r * 32 + j * 4);
        }
        CP_COMMIT();
    }
    #pragma unroll
    for (int cpre = 0; cpre < 2; cpre++) {
        const float* xsrcp = xr + xoff + (size_t)(cpre * KC) * HW;
        #pragma unroll
        for (int p = 0; p < 2; p++)
            px[p] = *(const float4*)(xsrcp + (size_t)(p * 16 + x_kw) * HW);
        float* xd = xs + cpre * XS_STAGE;
        #pragma unroll
        for (int p = 0; p < 2; p++) {
            float4 v = px[p];
            v.x = tf32r(v.x); v.y = tf32r(v.y); v.z = tf32r(v.z); v.w = tf32r(v.w);
            *(float4*)(xd + (p * 16 + x_kw) * XP + x_c4) = v;
        }
    }

    const int abase = (wr * 64 + ty) * WP + 2 * tx;     // + mt*16*WP + kk
    const int bbase = tx * XP + wc * 32 + ty;           // + kk*XP + nt*8

    for (int i = 0; i < 16; i++) {
        CP_WAIT1();
        __syncthreads();

        const int ki = i + 2;
        if (ki < 16) {
            const float* src = wsrc0 + (size_t)ki * 512 * 32;
            const uint32_t dst = ws_u32 + (ki % NSTG) * (WS_STAGE * 4);
            #pragma unroll
            for (int p = 0; p < 4; p++) {
                const int idx = p * 512 + tid;
                const int r = idx >> 3, j = idx & 7;
                CP_ASYNC16(dst + r * (WP * 4) + j * 16, src + r * 32 + j * 4);
            }
            const float* xsrcp = ((ki < 8) ? xr : xi) + xoff + (size_t)((ki & 7) * KC) * HW;
            #pragma unroll
            for (int p = 0; p < 2; p++)
                px[p] = *(const float4*)(xsrcp + (size_t)(p * 16 + x_kw) * HW);
        }
        CP_COMMIT();

        // ---- compute chunk i ----
        const float* wst = ws + (i % NSTG) * WS_STAGE;
        const float* xst = xs + (i % NSTG) * XS_STAGE;
        #pragma unroll
        for (int kk = 0; kk < KC; kk += 8) {
            float2 a2[4][2];
            #pragma unroll
            for (int mt = 0; mt < 4; mt++) {
                const float* ap = wst + abase + mt * (16 * WP) + kk;
                a2[mt][0] = *(const float2*)ap;
                a2[mt][1] = *(const float2*)(ap + 8 * WP);
            }
            uint32_t bf[4][2];
            #pragma unroll
            for (int nt = 0; nt < 4; nt++) {
                const float* bp = xst + bbase + kk * XP + nt * 8;
                bf[nt][0] = __float_as_uint(bp[0]);
                bf[nt][1] = __float_as_uint(bp[4 * XP]);
            }
            #pragma unroll
            for (int mt = 0; mt < 4; mt++) {
                const uint32_t a0 = __float_as_uint(a2[mt][0].x);
                const uint32_t a1 = __float_as_uint(a2[mt][1].x);
                const uint32_t a2r = __float_as_uint(a2[mt][0].y);
                const uint32_t a3 = __float_as_uint(a2[mt][1].y);
                #pragma unroll
                for (int nt = 0; nt < 4; nt++)
                    MMA_TF32(acc[mt][nt][0], acc[mt][nt][1], acc[mt][nt][2], acc[mt][nt][3],
                             a0, a1, a2r, a3, bf[nt][0], bf[nt][1]);
            }
        }

        // ---- X STS chunk ki ----
        if (ki < 16) {
            float* xd = xs + (ki % NSTG) * XS_STAGE;
            #pragma unroll
            for (int p = 0; p < 2; p++) {
                float4 v = px[p];
                v.x = tf32r(v.x); v.y = tf32r(v.y); v.z = tf32r(v.z); v.w = tf32r(v.w);
                *(float4*)(xd + (p * 16 + x_kw) * XP + x_c4) = v;
            }
        }
    }

    // ---- epilogue: direct STG.64 ----
    float* outp = out + ((size_t)(by * 4 + b) * NFFT) * (size_t)HW + c0 + wc * 32;
    #pragma unroll
    for (int mt = 0; mt < 4; mt++) {
        const int r0 = wr * 64 + mt * 16 + ty;
        #pragma unroll
        for (int nt = 0; nt < 4; nt++) {
            const int col = nt * 8 + tx * 2;
            float2 v0 = make_float2(acc[mt][nt][0], acc[mt][nt][1]);
            float2 v1 = make_float2(acc[mt][nt][2], acc[mt][nt][3]);
            *(float2*)(outp + (size_t)r0 * HW + col)       = v0;
            *(float2*)(outp + (size_t)(r0 + 8) * HW + col) = v1;
        }
    }
}

extern "C" void kernel_launch(void* const* d_in, const int* in_sizes, int n_in,
                              void* d_out, int out_size) {
    const float* xr = nullptr;
    const float* xi = nullptr;
    const float* w  = nullptr;
    for (int i = 0; i < n_in; i++) {
        if (in_sizes[i] == 4 * NFFT * HW) {
            if (!xr)      xr = (const float*)d_in[i];
            else if (!xi) xi = (const float*)d_in[i];
        } else if (in_sizes[i] == KTOT * KTOT) {
            w = (const float*)d_in[i];
        }
    }
    float* out = (float*)d_out;

    prep_w_kernel<<<1024, 256>>>(w);

    const int smem_bytes = NSTG * (WS_STAGE + XS_STAGE) * 4;   // 175,104
    cudaFuncSetAttribute(fft_hmma_kernel, cudaFuncAttributeMaxDynamicSharedMemorySize, smem_bytes);
    dim3 grid(HW / NT, 2, 4);   // (512, 2, 4)
    fft_hmma_kernel<<<grid, 512, smem_bytes>>>(xr, xi, out);
}